// round 2
// baseline (speedup 1.0000x reference)
#include <cuda_runtime.h>
#include <cuda_bf16.h>

// ---------------------------------------------------------------------------
// GCN: out = GC2( relu( GC1(X) ) ),  GC(x) = D_in^{-1/2} A^T ( D_out^{-1/2} x ) W + b
// Reordered: Y = (x * rs_out) @ W  first, then CSR gather-sum, then * rs_in + b.
// ---------------------------------------------------------------------------

#define MAXN 10000
#define MAXE 640000

__device__ int    g_cnt_in [MAXN];
__device__ int    g_cnt_out[MAXN];
__device__ int    g_rowptr [MAXN + 1];
__device__ int    g_cursor [MAXN];
__device__ int    g_esrc   [MAXE];
__device__ float  g_rsin   [MAXN];
__device__ float  g_rsout  [MAXN];
__device__ float4 g_Y1     [MAXN * 32];   // 10000 x 128 f32
__device__ float4 g_H1     [MAXN * 32];   // 10000 x 128 f32
__device__ float4 g_Y2     [MAXN * 16];   // 10000 x 64  f32
__device__ int    g_is64;

// ---------------------------------------------------------------------------
// init counters; block 0 additionally detects whether index dtype is int64 or
// int32 (int64 view of int32 data has huge/negative values with certainty
// over 256 samples).
__global__ void init_kernel(const void* __restrict__ src, int nnodes, int nedges) {
    int i = blockIdx.x * blockDim.x + threadIdx.x;
    if (i < nnodes) { g_cnt_in[i] = 0; g_cnt_out[i] = 0; }
    if (blockIdx.x == 0) {
        if (threadIdx.x == 0) g_is64 = 1;
        __syncthreads();
        int idx = (int)((threadIdx.x * 37u) % (unsigned)(nedges / 2));
        long long v = ((const long long*)src)[idx];
        if (v < 0 || v >= 1000000LL) atomicAnd(&g_is64, 0);
    }
}

__device__ __forceinline__ int load_idx(const void* p, int e, int is64) {
    return is64 ? (int)((const long long*)p)[e] : ((const int*)p)[e];
}

__global__ void hist_kernel(const void* __restrict__ src, const void* __restrict__ dst,
                            int nedges) {
    int is64 = g_is64;
    for (int e = blockIdx.x * blockDim.x + threadIdx.x; e < nedges;
         e += gridDim.x * blockDim.x) {
        atomicAdd(&g_cnt_out[load_idx(src, e, is64)], 1);
        atomicAdd(&g_cnt_in [load_idx(dst, e, is64)], 1);
    }
}

// ---------------------------------------------------------------------------
// Single-block warp-cooperative exclusive scan of g_cnt_in -> g_rowptr/cursor,
// fused with rsqrt degree-norm computation. Two passes of fully coalesced
// loads + 5-step shfl scans; only 2 block barriers.
// ---------------------------------------------------------------------------
__global__ void __launch_bounds__(1024) scan_kernel(int nnodes) {
    __shared__ int s_tot[32], s_off[32];
    int t = threadIdx.x, w = t >> 5, lane = t & 31;
    int G = (nnodes + 1023) / 1024;          // groups of 32 per warp (10)
    int base = w * G * 32;

    // pass 1: per-warp chunk total
    int sum = 0;
#pragma unroll 10
    for (int g = 0; g < G; ++g) {
        int idx = base + g * 32 + lane;
        sum += (idx < nnodes) ? g_cnt_in[idx] : 0;
    }
#pragma unroll
    for (int o = 16; o; o >>= 1) sum += __shfl_down_sync(0xffffffffu, sum, o);
    if (lane == 0) s_tot[w] = sum;
    __syncthreads();

    // warp 0: exclusive scan of 32 warp totals
    if (w == 0) {
        int v = s_tot[lane];
        int incl = v;
#pragma unroll
        for (int o = 1; o < 32; o <<= 1) {
            int u = __shfl_up_sync(0xffffffffu, incl, o);
            if (lane >= o) incl += u;
        }
        s_off[lane] = incl - v;
        if (lane == 31) g_rowptr[nnodes] = incl;
    }
    __syncthreads();

    // pass 2: per-element exclusive prefix + norms
    int run = s_off[w];
#pragma unroll 10
    for (int g = 0; g < G; ++g) {
        int idx = base + g * 32 + lane;
        int v = (idx < nnodes) ? g_cnt_in[idx] : 0;
        int incl = v;
#pragma unroll
        for (int o = 1; o < 32; o <<= 1) {
            int u = __shfl_up_sync(0xffffffffu, incl, o);
            if (lane >= o) incl += u;
        }
        if (idx < nnodes) {
            int excl = run + incl - v;
            g_rowptr[idx] = excl;
            g_cursor[idx] = excl;
            g_rsin[idx] = rsqrtf((float)(v > 1 ? v : 1));
            int co = g_cnt_out[idx];
            g_rsout[idx] = rsqrtf((float)(co > 1 ? co : 1));
        }
        run += __shfl_sync(0xffffffffu, incl, 31);
    }
}

__global__ void scatter_kernel(const void* __restrict__ src, const void* __restrict__ dst,
                               int nedges) {
    int is64 = g_is64;
    for (int e = blockIdx.x * blockDim.x + threadIdx.x; e < nedges;
         e += gridDim.x * blockDim.x) {
        int s = load_idx(src, e, is64);
        int d = load_idx(dst, e, is64);
        int pos = atomicAdd(&g_cursor[d], 1);
        g_esrc[pos] = s;
    }
}

// ---------------------------------------------------------------------------
// Dense GEMM: Y[r][c] = sum_k (X[r][k] * scale[r]) * W[k][c]
// LAYER 1: X=in_feat, scale=g_rsout, Y=g_Y1, 128 cols (two 64-row k-chunks of W in smem)
// LAYER 2: X=g_H1 (scale prefolded), Y=g_Y2, 64 cols (whole W in smem)
// 8 warps/block, 8 rows/warp register blocking: each smem W read feeds 8 FMAs.
// ---------------------------------------------------------------------------
template <int LAYER>
__global__ void __launch_bounds__(256) gemm_kernel(const float* __restrict__ Xext,
                                                   const float* __restrict__ W,
                                                   int nrows) {
    constexpr int NCOLS = (LAYER == 1) ? 128 : 64;
    constexpr int KC    = (LAYER == 1) ? 64  : 128;
    constexpr int NCH   = 128 / KC;
    constexpr int Q     = NCOLS / 32;
    constexpr int RPW   = 8;
    constexpr int RPB   = RPW * 8;   // 64 rows per block-iter

    __shared__ float Ws[KC * NCOLS];   // 32 KB

    const float* X = (LAYER == 1) ? Xext : (const float*)g_H1;
    float*       Y = (LAYER == 1) ? (float*)g_Y1 : (float*)g_Y2;

    int warp = threadIdx.x >> 5, lane = threadIdx.x & 31;

    for (int ch = 0; ch < NCH; ++ch) {
        for (int i = threadIdx.x; i < KC * NCOLS; i += blockDim.x) {
            int kk = i / NCOLS, cc = i % NCOLS;
            Ws[i] = W[(ch * KC + kk) * NCOLS + cc];
        }
        __syncthreads();

        for (int rbase = blockIdx.x * RPB + warp * RPW; rbase < nrows;
             rbase += gridDim.x * RPB) {
            float acc[RPW][Q];
#pragma unroll
            for (int r = 0; r < RPW; ++r)
#pragma unroll
                for (int q = 0; q < Q; ++q) acc[r][q] = 0.f;

            for (int kb = 0; kb < KC; kb += 32) {
                float xv[RPW];
#pragma unroll
                for (int r = 0; r < RPW; ++r) {
                    int row = rbase + r;
                    float v = 0.f;
                    if (row < nrows) {
                        v = X[row * 128 + ch * KC + kb + lane];
                        if (LAYER == 1) v *= g_rsout[row];
                    }
                    xv[r] = v;
                }
#pragma unroll
                for (int j = 0; j < 32; ++j) {
                    float a[RPW];
#pragma unroll
                    for (int r = 0; r < RPW; ++r)
                        a[r] = __shfl_sync(0xffffffffu, xv[r], j);
#pragma unroll
                    for (int q = 0; q < Q; ++q) {
                        float wv = Ws[(kb + j) * NCOLS + lane + 32 * q];
#pragma unroll
                        for (int r = 0; r < RPW; ++r)
                            acc[r][q] = fmaf(a[r], wv, acc[r][q]);
                    }
                }
            }
#pragma unroll
            for (int r = 0; r < RPW; ++r) {
                int row = rbase + r;
                if (row >= nrows) break;
#pragma unroll
                for (int q = 0; q < Q; ++q) {
                    int c = lane + 32 * q;
                    if (NCH == 1 || ch == 0) Y[row * NCOLS + c] = acc[r][q];
                    else                     Y[row * NCOLS + c] += acc[r][q];
                }
            }
        }
        __syncthreads();
    }
}

// ---------------------------------------------------------------------------
// CSR gather SpMM + fused epilogue.
// LAYER 1: in=g_Y1 (128 f), out=g_H1 = relu(sum*rs_in + b1) * rs_out
// LAYER 2: in=g_Y2 (64 f),  out=d_out = sum*rs_in + b2
// One float4 column-chunk per thread; 32 (or 16) consecutive lanes per node ->
// each edge's gather is a fully-coalesced 512B (256B) read from L2-resident Y.
// ---------------------------------------------------------------------------
template <int LAYER>
__global__ void __launch_bounds__(256) spmm_kernel(const float* __restrict__ bias,
                                                   float* __restrict__ outext,
                                                   int nnodes) {
    constexpr int F   = (LAYER == 1) ? 128 : 64;
    constexpr int LPN = F / 4;   // float4 chunks per node

    const float4* Yin = (LAYER == 1) ? (const float4*)g_Y1 : (const float4*)g_Y2;
    float4*       out = (LAYER == 1) ? (float4*)g_H1 : (float4*)outext;

    int gid  = blockIdx.x * blockDim.x + threadIdx.x;
    int node = gid / LPN;
    int c    = gid % LPN;
    if (node >= nnodes) return;

    int beg = g_rowptr[node];
    int end = g_rowptr[node + 1];

    float4 acc = make_float4(0.f, 0.f, 0.f, 0.f);
    int e = beg;
    for (; e + 3 < end; e += 4) {
        int s0 = g_esrc[e], s1 = g_esrc[e + 1], s2 = g_esrc[e + 2], s3 = g_esrc[e + 3];
        float4 v0 = Yin[s0 * LPN + c];
        float4 v1 = Yin[s1 * LPN + c];
        float4 v2 = Yin[s2 * LPN + c];
        float4 v3 = Yin[s3 * LPN + c];
        v0.x += v1.x; v0.y += v1.y; v0.z += v1.z; v0.w += v1.w;
        v2.x += v3.x; v2.y += v3.y; v2.z += v3.z; v2.w += v3.w;
        acc.x += v0.x + v2.x; acc.y += v0.y + v2.y;
        acc.z += v0.z + v2.z; acc.w += v0.w + v2.w;
    }
    for (; e < end; ++e) {
        int s = g_esrc[e];
        float4 v = Yin[s * LPN + c];
        acc.x += v.x; acc.y += v.y; acc.z += v.z; acc.w += v.w;
    }

    float  ri = g_rsin[node];
    float4 b  = ((const float4*)bias)[c];
    float4 r;
    r.x = fmaf(acc.x, ri, b.x);
    r.y = fmaf(acc.y, ri, b.y);
    r.z = fmaf(acc.z, ri, b.z);
    r.w = fmaf(acc.w, ri, b.w);
    if (LAYER == 1) {
        float ro = g_rsout[node];
        r.x = fmaxf(r.x, 0.f) * ro;
        r.y = fmaxf(r.y, 0.f) * ro;
        r.z = fmaxf(r.z, 0.f) * ro;
        r.w = fmaxf(r.w, 0.f) * ro;
    }
    out[node * LPN + c] = r;
}

// ---------------------------------------------------------------------------

extern "C" void kernel_launch(void* const* d_in, const int* in_sizes, int n_in,
                              void* d_out, int out_size) {
    const float* in_feat = (const float*)d_in[0];
    const void*  src     = d_in[1];
    const void*  dst     = d_in[2];
    const float* W1      = (const float*)d_in[3];
    const float* b1      = (const float*)d_in[4];
    const float* W2      = (const float*)d_in[5];
    const float* b2      = (const float*)d_in[6];

    int nnodes = in_sizes[0] / 128;   // 10000
    int nedges = in_sizes[1];         // 640000

    const int TB = 256;

    init_kernel<<<(nnodes + TB - 1) / TB, TB>>>(src, nnodes, nedges);
    hist_kernel<<<240, TB>>>(src, dst, nedges);
    scan_kernel<<<1, 1024>>>(nnodes);
    scatter_kernel<<<240, TB>>>(src, dst, nedges);

    int gemm_blocks = (nnodes + 63) / 64;
    gemm_kernel<1><<<gemm_blocks, 256>>>(in_feat, W1, nnodes);
    spmm_kernel<1><<<(nnodes * 32 + TB - 1) / TB, TB>>>(b1, nullptr, nnodes);
    gemm_kernel<2><<<gemm_blocks, 256>>>(nullptr, W2, nnodes);
    spmm_kernel<2><<<(nnodes * 16 + TB - 1) / TB, TB>>>(b2, (float*)d_out, nnodes);
}

// round 5
// speedup vs baseline: 1.4828x; 1.4828x over previous
#include <cuda_runtime.h>
#include <cuda_bf16.h>

// ---------------------------------------------------------------------------
// GCN: out = GC2( relu( GC1(X) ) ),  GC(x) = D_in^{-1/2} A^T ( D_out^{-1/2} x ) W + b
// Reordered: Y = (x * rs_out) @ W  first, then CSR gather-sum, then * rs_in + b.
// ---------------------------------------------------------------------------

#define MAXN 10000
#define MAXE 640000

__device__ int    g_cnt_in [MAXN];
__device__ int    g_cnt_out[MAXN];
__device__ int    g_rowptr [MAXN + 1];
__device__ int    g_cursor [MAXN];
__device__ int    g_esrc   [MAXE];
__device__ float  g_rsin   [MAXN];
__device__ float  g_rsout  [MAXN];
__device__ float4 g_Y1     [MAXN * 32];   // 10000 x 128 f32
__device__ float4 g_H1     [MAXN * 32];   // 10000 x 128 f32
__device__ float4 g_Y2     [MAXN * 16];   // 10000 x 64  f32
__device__ int    g_is64;

// ---------------------------------------------------------------------------
// init counters; block 0 additionally detects whether index dtype is int64 or
// int32 (int64 view of int32 data has huge/negative values with certainty
// over 256 samples).
__global__ void init_kernel(const void* __restrict__ src, int nnodes, int nedges) {
    int i = blockIdx.x * blockDim.x + threadIdx.x;
    if (i < nnodes) { g_cnt_in[i] = 0; g_cnt_out[i] = 0; }
    if (blockIdx.x == 0) {
        if (threadIdx.x == 0) g_is64 = 1;
        __syncthreads();
        int idx = (int)((threadIdx.x * 37u) % (unsigned)(nedges / 2));
        long long v = ((const long long*)src)[idx];
        if (v < 0 || v >= 1000000LL) atomicAnd(&g_is64, 0);
    }
}

__device__ __forceinline__ int load_idx(const void* p, int e, int is64) {
    return is64 ? (int)((const long long*)p)[e] : ((const int*)p)[e];
}

// one edge per thread — maximize warps in flight to hide idx-load + ATOMG latency
__global__ void hist_kernel(const void* __restrict__ src, const void* __restrict__ dst,
                            int nedges) {
    int e = blockIdx.x * blockDim.x + threadIdx.x;
    if (e >= nedges) return;
    int is64 = g_is64;
    atomicAdd(&g_cnt_out[load_idx(src, e, is64)], 1);
    atomicAdd(&g_cnt_in [load_idx(dst, e, is64)], 1);
}

// ---------------------------------------------------------------------------
// Single-block warp-cooperative exclusive scan of g_cnt_in -> g_rowptr/cursor,
// fused with rsqrt degree-norm computation. Two passes of fully coalesced
// loads + 5-step shfl scans; only 2 block barriers.
// ---------------------------------------------------------------------------
__global__ void __launch_bounds__(1024) scan_kernel(int nnodes) {
    __shared__ int s_tot[32], s_off[32];
    int t = threadIdx.x, w = t >> 5, lane = t & 31;
    int G = (nnodes + 1023) / 1024;          // groups of 32 per warp (10)
    int base = w * G * 32;

    // pass 1: per-warp chunk total
    int sum = 0;
#pragma unroll 10
    for (int g = 0; g < G; ++g) {
        int idx = base + g * 32 + lane;
        sum += (idx < nnodes) ? g_cnt_in[idx] : 0;
    }
#pragma unroll
    for (int o = 16; o; o >>= 1) sum += __shfl_down_sync(0xffffffffu, sum, o);
    if (lane == 0) s_tot[w] = sum;
    __syncthreads();

    // warp 0: exclusive scan of 32 warp totals
    if (w == 0) {
        int v = s_tot[lane];
        int incl = v;
#pragma unroll
        for (int o = 1; o < 32; o <<= 1) {
            int u = __shfl_up_sync(0xffffffffu, incl, o);
            if (lane >= o) incl += u;
        }
        s_off[lane] = incl - v;
        if (lane == 31) g_rowptr[nnodes] = incl;
    }
    __syncthreads();

    // pass 2: per-element exclusive prefix + norms
    int run = s_off[w];
#pragma unroll 10
    for (int g = 0; g < G; ++g) {
        int idx = base + g * 32 + lane;
        int v = (idx < nnodes) ? g_cnt_in[idx] : 0;
        int incl = v;
#pragma unroll
        for (int o = 1; o < 32; o <<= 1) {
            int u = __shfl_up_sync(0xffffffffu, incl, o);
            if (lane >= o) incl += u;
        }
        if (idx < nnodes) {
            int excl = run + incl - v;
            g_rowptr[idx] = excl;
            g_cursor[idx] = excl;
            g_rsin[idx] = rsqrtf((float)(v > 1 ? v : 1));
            int co = g_cnt_out[idx];
            g_rsout[idx] = rsqrtf((float)(co > 1 ? co : 1));
        }
        run += __shfl_sync(0xffffffffu, incl, 31);
    }
}

// one edge per thread
__global__ void scatter_kernel(const void* __restrict__ src, const void* __restrict__ dst,
                               int nedges) {
    int e = blockIdx.x * blockDim.x + threadIdx.x;
    if (e >= nedges) return;
    int is64 = g_is64;
    int s = load_idx(src, e, is64);
    int d = load_idx(dst, e, is64);
    int pos = atomicAdd(&g_cursor[d], 1);
    g_esrc[pos] = s;
}

// ---------------------------------------------------------------------------
// Dense GEMM: Y[r][c] = sum_k (X[r][k] * scale[r]) * W[k][c]
// LAYER 1: X=in_feat, scale=g_rsout, Y=g_Y1, 128 cols (two 64-row k-chunks of W in smem)
// LAYER 2: X=g_H1 (scale prefolded), Y=g_Y2, 64 cols (whole W in smem)
// 8 warps/block, 4 rows/warp register blocking (measured-good R1 config).
// ---------------------------------------------------------------------------
template <int LAYER>
__global__ void __launch_bounds__(256) gemm_kernel(const float* __restrict__ Xext,
                                                   const float* __restrict__ W,
                                                   int nrows) {
    constexpr int NCOLS = (LAYER == 1) ? 128 : 64;
    constexpr int KC    = (LAYER == 1) ? 64  : 128;
    constexpr int NCH   = 128 / KC;
    constexpr int Q     = NCOLS / 32;
    constexpr int RPW   = 4;
    constexpr int RPB   = RPW * 8;   // 32 rows per block-iter

    __shared__ float Ws[KC * NCOLS];   // 32 KB

    const float* X = (LAYER == 1) ? Xext : (const float*)g_H1;
    float*       Y = (LAYER == 1) ? (float*)g_Y1 : (float*)g_Y2;

    int warp = threadIdx.x >> 5, lane = threadIdx.x & 31;

    for (int ch = 0; ch < NCH; ++ch) {
        for (int i = threadIdx.x; i < KC * NCOLS; i += blockDim.x) {
            int kk = i / NCOLS, cc = i % NCOLS;
            Ws[i] = W[(ch * KC + kk) * NCOLS + cc];
        }
        __syncthreads();

        for (int rbase = blockIdx.x * RPB + warp * RPW; rbase < nrows;
             rbase += gridDim.x * RPB) {
            float acc[RPW][Q];
#pragma unroll
            for (int r = 0; r < RPW; ++r)
#pragma unroll
                for (int q = 0; q < Q; ++q) acc[r][q] = 0.f;

            for (int kb = 0; kb < KC; kb += 32) {
                float xv[RPW];
#pragma unroll
                for (int r = 0; r < RPW; ++r) {
                    int row = rbase + r;
                    float v = 0.f;
                    if (row < nrows) {
                        v = X[row * 128 + ch * KC + kb + lane];
                        if (LAYER == 1) v *= g_rsout[row];
                    }
                    xv[r] = v;
                }
#pragma unroll
                for (int j = 0; j < 32; ++j) {
                    float a[RPW];
#pragma unroll
                    for (int r = 0; r < RPW; ++r)
                        a[r] = __shfl_sync(0xffffffffu, xv[r], j);
#pragma unroll
                    for (int q = 0; q < Q; ++q) {
                        float wv = Ws[(kb + j) * NCOLS + lane + 32 * q];
#pragma unroll
                        for (int r = 0; r < RPW; ++r)
                            acc[r][q] = fmaf(a[r], wv, acc[r][q]);
                    }
                }
            }
#pragma unroll
            for (int r = 0; r < RPW; ++r) {
                int row = rbase + r;
                if (row >= nrows) break;
#pragma unroll
                for (int q = 0; q < Q; ++q) {
                    int c = lane + 32 * q;
                    if (NCH == 1 || ch == 0) Y[row * NCOLS + c] = acc[r][q];
                    else                     Y[row * NCOLS + c] += acc[r][q];
                }
            }
        }
        __syncthreads();
    }
}

// ---------------------------------------------------------------------------
// CSR gather SpMM + fused epilogue.
// LAYER 1: in=g_Y1 (128 f), out=g_H1 = relu(sum*rs_in + b1) * rs_out
// LAYER 2: in=g_Y2 (64 f),  out=d_out = sum*rs_in + b2
// One float4 column-chunk per thread; 32 (or 16) consecutive lanes per node ->
// each edge's gather is a fully-coalesced 512B (256B) read from L2-resident Y.
// ---------------------------------------------------------------------------
template <int LAYER>
__global__ void __launch_bounds__(256) spmm_kernel(const float* __restrict__ bias,
                                                   float* __restrict__ outext,
                                                   int nnodes) {
    constexpr int F   = (LAYER == 1) ? 128 : 64;
    constexpr int LPN = F / 4;   // float4 chunks per node

    const float4* Yin = (LAYER == 1) ? (const float4*)g_Y1 : (const float4*)g_Y2;
    float4*       out = (LAYER == 1) ? (float4*)g_H1 : (float4*)outext;

    int gid  = blockIdx.x * blockDim.x + threadIdx.x;
    int node = gid / LPN;
    int c    = gid % LPN;
    if (node >= nnodes) return;

    int beg = g_rowptr[node];
    int end = g_rowptr[node + 1];

    float4 acc = make_float4(0.f, 0.f, 0.f, 0.f);
    int e = beg;
    for (; e + 3 < end; e += 4) {
        int s0 = g_esrc[e], s1 = g_esrc[e + 1], s2 = g_esrc[e + 2], s3 = g_esrc[e + 3];
        float4 v0 = Yin[s0 * LPN + c];
        float4 v1 = Yin[s1 * LPN + c];
        float4 v2 = Yin[s2 * LPN + c];
        float4 v3 = Yin[s3 * LPN + c];
        v0.x += v1.x; v0.y += v1.y; v0.z += v1.z; v0.w += v1.w;
        v2.x += v3.x; v2.y += v3.y; v2.z += v3.z; v2.w += v3.w;
        acc.x += v0.x + v2.x; acc.y += v0.y + v2.y;
        acc.z += v0.z + v2.z; acc.w += v0.w + v2.w;
    }
    for (; e < end; ++e) {
        int s = g_esrc[e];
        float4 v = Yin[s * LPN + c];
        acc.x += v.x; acc.y += v.y; acc.z += v.z; acc.w += v.w;
    }

    float  ri = g_rsin[node];
    float4 b  = ((const float4*)bias)[c];
    float4 r;
    r.x = fmaf(acc.x, ri, b.x);
    r.y = fmaf(acc.y, ri, b.y);
    r.z = fmaf(acc.z, ri, b.z);
    r.w = fmaf(acc.w, ri, b.w);
    if (LAYER == 1) {
        float ro = g_rsout[node];
        r.x = fmaxf(r.x, 0.f) * ro;
        r.y = fmaxf(r.y, 0.f) * ro;
        r.z = fmaxf(r.z, 0.f) * ro;
        r.w = fmaxf(r.w, 0.f) * ro;
    }
    out[node * LPN + c] = r;
}

// ---------------------------------------------------------------------------

extern "C" void kernel_launch(void* const* d_in, const int* in_sizes, int n_in,
                              void* d_out, int out_size) {
    const float* in_feat = (const float*)d_in[0];
    const void*  src     = d_in[1];
    const void*  dst     = d_in[2];
    const float* W1      = (const float*)d_in[3];
    const float* b1      = (const float*)d_in[4];
    const float* W2      = (const float*)d_in[5];
    const float* b2      = (const float*)d_in[6];

    int nnodes = in_sizes[0] / 128;   // 10000
    int nedges = in_sizes[1];         // 640000

    const int TB = 256;
    int edge_blocks = (nedges + TB - 1) / TB;   // 2500

    init_kernel<<<(nnodes + TB - 1) / TB, TB>>>(src, nnodes, nedges);
    hist_kernel<<<edge_blocks, TB>>>(src, dst, nedges);
    scan_kernel<<<1, 1024>>>(nnodes);
    scatter_kernel<<<edge_blocks, TB>>>(src, dst, nedges);

    int gemm_blocks = (nnodes + 31) / 32;
    gemm_kernel<1><<<gemm_blocks, 256>>>(in_feat, W1, nnodes);
    spmm_kernel<1><<<(nnodes * 32 + TB - 1) / TB, TB>>>(b1, nullptr, nnodes);
    gemm_kernel<2><<<gemm_blocks, 256>>>(nullptr, W2, nnodes);
    spmm_kernel<2><<<(nnodes * 16 + TB - 1) / TB, TB>>>(b2, (float*)d_out, nnodes);
}

// round 9
// speedup vs baseline: 1.5599x; 1.0520x over previous
#include <cuda_runtime.h>
#include <cuda_bf16.h>
#include <cuda_fp16.h>

// ---------------------------------------------------------------------------
// GCN: out = GC2( relu( GC1(X) ) ),  GC(x) = D_in^{-1/2} A^T ( D_out^{-1/2} x ) W + b
// Reordered: Y = (x * rs_out) @ W  first (fp16 output), then CSR gather-sum
// (fp32 accumulate), then * rs_in + b.
// ---------------------------------------------------------------------------

#define MAXN 10000
#define MAXE 640000

__device__ int    g_cnt_in [MAXN];
__device__ int    g_cnt_out[MAXN];
__device__ int    g_rowptr [MAXN + 1];
__device__ int    g_cursor [MAXN];
__device__ int    g_esrc   [MAXE];
__device__ float  g_rsin   [MAXN];
__device__ float  g_rsout  [MAXN];
__device__ __half g_Y1h    [MAXN * 128];  // fp16 gather buffer, layer 1
__device__ __half g_Y2h    [MAXN * 64];   // fp16 gather buffer, layer 2
__device__ float4 g_H1     [MAXN * 32];   // 10000 x 128 f32 (gemm2 input)
__device__ int    g_is64;

// ---------------------------------------------------------------------------
__global__ void init_kernel(const void* __restrict__ src, int nnodes, int nedges) {
    int i = blockIdx.x * blockDim.x + threadIdx.x;
    if (i < nnodes) { g_cnt_in[i] = 0; g_cnt_out[i] = 0; }
    if (blockIdx.x == 0) {
        if (threadIdx.x == 0) g_is64 = 1;
        __syncthreads();
        int idx = (int)((threadIdx.x * 37u) % (unsigned)(nedges / 2));
        long long v = ((const long long*)src)[idx];
        if (v < 0 || v >= 1000000LL) atomicAnd(&g_is64, 0);
    }
}

__device__ __forceinline__ int load_idx(const void* p, int e, int is64) {
    return is64 ? (int)((const long long*)p)[e] : ((const int*)p)[e];
}

// two independent edges per thread: two overlapped LDG->ATOM chains
__global__ void hist_kernel(const void* __restrict__ src, const void* __restrict__ dst,
                            int nedges) {
    int h = (nedges + 1) >> 1;
    int e0 = blockIdx.x * blockDim.x + threadIdx.x;
    if (e0 >= h) return;
    int e1 = e0 + h;
    int is64 = g_is64;
    int s0 = load_idx(src, e0, is64);
    int d0 = load_idx(dst, e0, is64);
    int s1 = -1, d1 = -1;
    if (e1 < nedges) { s1 = load_idx(src, e1, is64); d1 = load_idx(dst, e1, is64); }
    atomicAdd(&g_cnt_out[s0], 1);
    atomicAdd(&g_cnt_in [d0], 1);
    if (e1 < nedges) {
        atomicAdd(&g_cnt_out[s1], 1);
        atomicAdd(&g_cnt_in [d1], 1);
    }
}

// ---------------------------------------------------------------------------
// Single-block warp-cooperative exclusive scan + degree norms.
// ---------------------------------------------------------------------------
__global__ void __launch_bounds__(1024) scan_kernel(int nnodes) {
    __shared__ int s_tot[32], s_off[32];
    int t = threadIdx.x, w = t >> 5, lane = t & 31;
    int G = (nnodes + 1023) / 1024;
    int base = w * G * 32;

    int sum = 0;
#pragma unroll 10
    for (int g = 0; g < G; ++g) {
        int idx = base + g * 32 + lane;
        sum += (idx < nnodes) ? g_cnt_in[idx] : 0;
    }
#pragma unroll
    for (int o = 16; o; o >>= 1) sum += __shfl_down_sync(0xffffffffu, sum, o);
    if (lane == 0) s_tot[w] = sum;
    __syncthreads();

    if (w == 0) {
        int v = s_tot[lane];
        int incl = v;
#pragma unroll
        for (int o = 1; o < 32; o <<= 1) {
            int u = __shfl_up_sync(0xffffffffu, incl, o);
            if (lane >= o) incl += u;
        }
        s_off[lane] = incl - v;
        if (lane == 31) g_rowptr[nnodes] = incl;
    }
    __syncthreads();

    int run = s_off[w];
#pragma unroll 10
    for (int g = 0; g < G; ++g) {
        int idx = base + g * 32 + lane;
        int v = (idx < nnodes) ? g_cnt_in[idx] : 0;
        int incl = v;
#pragma unroll
        for (int o = 1; o < 32; o <<= 1) {
            int u = __shfl_up_sync(0xffffffffu, incl, o);
            if (lane >= o) incl += u;
        }
        if (idx < nnodes) {
            int excl = run + incl - v;
            g_rowptr[idx] = excl;
            g_cursor[idx] = excl;
            g_rsin[idx] = rsqrtf((float)(v > 1 ? v : 1));
            int co = g_cnt_out[idx];
            g_rsout[idx] = rsqrtf((float)(co > 1 ? co : 1));
        }
        run += __shfl_sync(0xffffffffu, incl, 31);
    }
}

// two independent edges per thread
__global__ void scatter_kernel(const void* __restrict__ src, const void* __restrict__ dst,
                               int nedges) {
    int h = (nedges + 1) >> 1;
    int e0 = blockIdx.x * blockDim.x + threadIdx.x;
    if (e0 >= h) return;
    int e1 = e0 + h;
    int is64 = g_is64;
    int s0 = load_idx(src, e0, is64);
    int d0 = load_idx(dst, e0, is64);
    int s1 = -1, d1 = -1;
    if (e1 < nedges) { s1 = load_idx(src, e1, is64); d1 = load_idx(dst, e1, is64); }
    int p0 = atomicAdd(&g_cursor[d0], 1);
    int p1 = (e1 < nedges) ? atomicAdd(&g_cursor[d1], 1) : 0;
    g_esrc[p0] = s0;
    if (e1 < nedges) g_esrc[p1] = s1;
}

// ---------------------------------------------------------------------------
// Dense GEMM: Yh[r][c] = fp16( sum_k (X[r][k]*scale[r]) * W[k][c] )
// Full 128-row W in dynamic smem (64KB L1 / 32KB L2). Thread owns Q
// CONSECUTIVE columns -> one LDS.128/LDS.64 per k-step, conflict-free.
// 8 warps, 4 rows/warp register blocking (measured-good).
// ---------------------------------------------------------------------------
template <int LAYER>
__global__ void __launch_bounds__(256) gemm_kernel(const float* __restrict__ Xext,
                                                   const float* __restrict__ W,
                                                   int nrows) {
    constexpr int NCOLS = (LAYER == 1) ? 128 : 64;
    constexpr int Q     = NCOLS / 32;      // 4 or 2
    constexpr int RPW   = 4;
    constexpr int RPB   = RPW * 8;         // 32 rows per block-iter

    extern __shared__ float Ws[];          // 128*NCOLS floats

    const float* X  = (LAYER == 1) ? Xext : (const float*)g_H1;
    __half*      Yh = (LAYER == 1) ? g_Y1h : g_Y2h;

    int warp = threadIdx.x >> 5, lane = threadIdx.x & 31;

    for (int i = threadIdx.x; i < 128 * NCOLS; i += blockDim.x) Ws[i] = W[i];
    __syncthreads();

    for (int rbase = blockIdx.x * RPB + warp * RPW; rbase < nrows;
         rbase += gridDim.x * RPB) {
        float acc[RPW][Q];
#pragma unroll
        for (int r = 0; r < RPW; ++r)
#pragma unroll
            for (int q = 0; q < Q; ++q) acc[r][q] = 0.f;

        for (int kb = 0; kb < 128; kb += 32) {
            float xv[RPW];
#pragma unroll
            for (int r = 0; r < RPW; ++r) {
                int row = rbase + r;
                float v = 0.f;
                if (row < nrows) {
                    v = X[row * 128 + kb + lane];
                    if (LAYER == 1) v *= g_rsout[row];
                }
                xv[r] = v;
            }
#pragma unroll
            for (int j = 0; j < 32; ++j) {
                float a[RPW];
#pragma unroll
                for (int r = 0; r < RPW; ++r)
                    a[r] = __shfl_sync(0xffffffffu, xv[r], j);
                if (Q == 4) {
                    float4 wv = *(const float4*)&Ws[(kb + j) * NCOLS + (lane << 2)];
#pragma unroll
                    for (int r = 0; r < RPW; ++r) {
                        acc[r][0] = fmaf(a[r], wv.x, acc[r][0]);
                        acc[r][1] = fmaf(a[r], wv.y, acc[r][1]);
                        acc[r][2] = fmaf(a[r], wv.z, acc[r][2]);
                        acc[r][3] = fmaf(a[r], wv.w, acc[r][3]);
                    }
                } else {
                    float2 wv = *(const float2*)&Ws[(kb + j) * NCOLS + (lane << 1)];
#pragma unroll
                    for (int r = 0; r < RPW; ++r) {
                        acc[r][0] = fmaf(a[r], wv.x, acc[r][0]);
                        acc[r][1] = fmaf(a[r], wv.y, acc[r][1]);
                    }
                }
            }
        }
#pragma unroll
        for (int r = 0; r < RPW; ++r) {
            int row = rbase + r;
            if (row >= nrows) break;
            if (Q == 4) {
                __half2 p0 = __floats2half2_rn(acc[r][0], acc[r][1]);
                __half2 p1 = __floats2half2_rn(acc[r][2], acc[r][3]);
                __half2* dstp = (__half2*)(Yh + row * NCOLS) + (lane << 1);
                dstp[0] = p0;
                dstp[1] = p1;
            } else {
                __half2 p0 = __floats2half2_rn(acc[r][0], acc[r][1]);
                ((__half2*)(Yh + row * NCOLS))[lane] = p0;
            }
        }
    }
}

// ---------------------------------------------------------------------------
// CSR gather SpMM (fp16 in, fp32 accumulate) + fused epilogue.
// LAYER 1: in=g_Y1h (128 h), out=g_H1 = relu(sum*rs_in + b1) * rs_out   [fp32]
// LAYER 2: in=g_Y2h (64 h),  out=d_out = sum*rs_in + b2                 [fp32]
// Thread owns one 16B chunk (8 halves); LPN consecutive lanes per node ->
// each edge gather is a coalesced 256B (128B) L2-resident read.
// ---------------------------------------------------------------------------
template <int LAYER>
__global__ void __launch_bounds__(256) spmm_kernel(const float* __restrict__ bias,
                                                   float* __restrict__ outext,
                                                   int nnodes) {
    constexpr int F   = (LAYER == 1) ? 128 : 64;
    constexpr int LPN = F / 8;   // uint4 (8-half) chunks per node: 16 or 8

    const uint4* Yin = (LAYER == 1) ? (const uint4*)g_Y1h : (const uint4*)g_Y2h;
    float*       out = (LAYER == 1) ? (float*)g_H1 : outext;

    int gid  = blockIdx.x * blockDim.x + threadIdx.x;
    int node = gid / LPN;
    int c    = gid % LPN;
    if (node >= nnodes) return;

    int beg = g_rowptr[node];
    int end = g_rowptr[node + 1];

    float acc[8];
#pragma unroll
    for (int i = 0; i < 8; ++i) acc[i] = 0.f;

#define ACCUM(v)                                                        \
    do {                                                                \
        __half2* hp = (__half2*)&(v);                                   \
        float2 f0 = __half22float2(hp[0]);                              \
        float2 f1 = __half22float2(hp[1]);                              \
        float2 f2 = __half22float2(hp[2]);                              \
        float2 f3 = __half22float2(hp[3]);                              \
        acc[0] += f0.x; acc[1] += f0.y; acc[2] += f1.x; acc[3] += f1.y; \
        acc[4] += f2.x; acc[5] += f2.y; acc[6] += f3.x; acc[7] += f3.y; \
    } while (0)

    int e = beg;
    for (; e + 3 < end; e += 4) {
        int s0 = g_esrc[e], s1 = g_esrc[e + 1], s2 = g_esrc[e + 2], s3 = g_esrc[e + 3];
        uint4 v0 = Yin[s0 * LPN + c];
        uint4 v1 = Yin[s1 * LPN + c];
        uint4 v2 = Yin[s2 * LPN + c];
        uint4 v3 = Yin[s3 * LPN + c];
        ACCUM(v0); ACCUM(v1); ACCUM(v2); ACCUM(v3);
    }
    for (; e < end; ++e) {
        uint4 v = Yin[g_esrc[e] * LPN + c];
        ACCUM(v);
    }
#undef ACCUM

    float  ri = g_rsin[node];
    const float4* b4 = (const float4*)bias + c * 2;
    float4 ba = b4[0], bb = b4[1];
    float r0 = fmaf(acc[0], ri, ba.x), r1 = fmaf(acc[1], ri, ba.y);
    float r2 = fmaf(acc[2], ri, ba.z), r3 = fmaf(acc[3], ri, ba.w);
    float r4 = fmaf(acc[4], ri, bb.x), r5 = fmaf(acc[5], ri, bb.y);
    float r6 = fmaf(acc[6], ri, bb.z), r7 = fmaf(acc[7], ri, bb.w);
    if (LAYER == 1) {
        float ro = g_rsout[node];
        r0 = fmaxf(r0, 0.f) * ro; r1 = fmaxf(r1, 0.f) * ro;
        r2 = fmaxf(r2, 0.f) * ro; r3 = fmaxf(r3, 0.f) * ro;
        r4 = fmaxf(r4, 0.f) * ro; r5 = fmaxf(r5, 0.f) * ro;
        r6 = fmaxf(r6, 0.f) * ro; r7 = fmaxf(r7, 0.f) * ro;
    }
    float4* op = (float4*)(out + node * F + c * 8);
    op[0] = make_float4(r0, r1, r2, r3);
    op[1] = make_float4(r4, r5, r6, r7);
}

// ---------------------------------------------------------------------------

extern "C" void kernel_launch(void* const* d_in, const int* in_sizes, int n_in,
                              void* d_out, int out_size) {
    const float* in_feat = (const float*)d_in[0];
    const void*  src     = d_in[1];
    const void*  dst     = d_in[2];
    const float* W1      = (const float*)d_in[3];
    const float* b1      = (const float*)d_in[4];
    const float* W2      = (const float*)d_in[5];
    const float* b2      = (const float*)d_in[6];

    int nnodes = in_sizes[0] / 128;   // 10000
    int nedges = in_sizes[1];         // 640000

    const int TB = 256;
    int half_edges  = (nedges + 1) / 2;
    int edge_blocks = (half_edges + TB - 1) / TB;   // 1250

    cudaFuncSetAttribute(gemm_kernel<1>, cudaFuncAttributeMaxDynamicSharedMemorySize,
                         128 * 128 * 4);

    init_kernel<<<(nnodes + TB - 1) / TB, TB>>>(src, nnodes, nedges);
    hist_kernel<<<edge_blocks, TB>>>(src, dst, nedges);
    scan_kernel<<<1, 1024>>>(nnodes);
    scatter_kernel<<<edge_blocks, TB>>>(src, dst, nedges);

    int gemm_blocks = (nnodes + 31) / 32;
    gemm_kernel<1><<<gemm_blocks, 256, 128 * 128 * 4>>>(in_feat, W1, nnodes);
    spmm_kernel<1><<<(nnodes * 16 + TB - 1) / TB, TB>>>(b1, nullptr, nnodes);
    gemm_kernel<2><<<gemm_blocks, 256, 128 * 64 * 4>>>(nullptr, W2, nnodes);
    spmm_kernel<2><<<(nnodes * 8 + TB - 1) / TB, TB>>>(b2, (float*)d_out, nnodes);
}